// round 15
// baseline (speedup 1.0000x reference)
#include <cuda_runtime.h>
#include <cstdint>

// Problem constants (fixed by the dataset)
#define N_NODES 50000
#define N_EDGES 800000
#define IN_C    512
#define HID_C   512
#define OUT_C   256

#define SCAN_BLK 512
#define NB_SCAN  ((N_NODES + SCAN_BLK - 1) / SCAN_BLK)   // 98

// ---------------------------------------------------------------------------
// Scratch: __device__ globals, referenced directly inside kernels.
// (No tensor-core instructions anywhere: any module containing ldmatrix /
// mma.sync triggers a fixed 128MiB driver-side allocation on this stack,
// which the harness's memory tracker vetoes. Verified rounds 7-13.)
// ---------------------------------------------------------------------------
__device__ int   g_is64;                            // 1 if edge_index is int64
__device__ int   g_cnt   [N_NODES];
__device__ int   g_fill  [N_NODES];
__device__ int   g_rowptr[N_NODES + 1];
__device__ int   g_blksum[128];                     // NB_SCAN <= 128
__device__ int   g_col   [N_EDGES];
__device__ float g_dinv  [N_NODES];
__device__ float g_Hs1   [(size_t)N_NODES * HID_C]; // X @ W1 (unscaled)
__device__ float g_X1    [(size_t)N_NODES * HID_C]; // relu layer-1 output
__device__ float g_Hs2   [(size_t)N_NODES * OUT_C]; // X1 @ W2 (unscaled)

// ---------------------------------------------------------------------------
// Edge-index dtype probe (int64 vs int32 staging — fixed the 717 trap)
// ---------------------------------------------------------------------------
__global__ void k_detect(const int* __restrict__ ei32) {
    if (blockIdx.x != 0 || threadIdx.x != 0) return;
    int allzero = 1;
    #pragma unroll 1
    for (int i = 1; i < 256; i += 2) {
        if (ei32[i] != 0) { allzero = 0; break; }
    }
    g_is64 = allzero;
}

__device__ __forceinline__ int edge_at(const void* ei, int e, int which) {
    int v;
    if (g_is64) {
        const long long* p = (const long long*)ei;
        v = (int)p[(size_t)which * N_EDGES + e];
    } else {
        const int* p = (const int*)ei;
        v = p[(size_t)which * N_EDGES + e];
    }
    v = (v < 0) ? 0 : v;
    v = (v >= N_NODES) ? (N_NODES - 1) : v;
    return v;
}

// ---------------------------------------------------------------------------
// CSR build: count -> scan -> fill  (int atomics only)
// ---------------------------------------------------------------------------
__global__ void k_prep() {
    int i = blockIdx.x * blockDim.x + threadIdx.x;
    if (i < N_NODES) { g_cnt[i] = 0; g_fill[i] = 0; }
}

__global__ void k_count(const void* __restrict__ ei) {
    int e = blockIdx.x * blockDim.x + threadIdx.x;
    if (e < N_EDGES) atomicAdd(&g_cnt[edge_at(ei, e, 1)], 1);
}

__global__ void k_dinv() {
    int i = blockIdx.x * blockDim.x + threadIdx.x;
    if (i < N_NODES) g_dinv[i] = rsqrtf(1.0f + (float)g_cnt[i]);  // +1 self loop
}

__global__ void k_scan1() {
    __shared__ int sh[SCAN_BLK];
    const int t = threadIdx.x;
    const int i = blockIdx.x * SCAN_BLK + t;
    int v = (i < N_NODES) ? g_cnt[i] : 0;
    sh[t] = v;
    __syncthreads();
    #pragma unroll
    for (int off = 1; off < SCAN_BLK; off <<= 1) {
        int x = (t >= off) ? sh[t - off] : 0;
        __syncthreads();
        sh[t] += x;
        __syncthreads();
    }
    if (i < N_NODES) g_rowptr[i] = sh[t] - v;
    if (t == SCAN_BLK - 1) g_blksum[blockIdx.x] = sh[t];
}

__global__ void k_scan2() {
    __shared__ int sh[128];
    const int t = threadIdx.x;
    int v = (t < NB_SCAN) ? g_blksum[t] : 0;
    sh[t] = v;
    __syncthreads();
    #pragma unroll
    for (int off = 1; off < 128; off <<= 1) {
        int x = (t >= off) ? sh[t - off] : 0;
        __syncthreads();
        sh[t] += x;
        __syncthreads();
    }
    if (t < NB_SCAN) g_blksum[t] = sh[t] - v;
}

__global__ void k_scan3() {
    int i = blockIdx.x * blockDim.x + threadIdx.x;
    if (i < N_NODES) g_rowptr[i] += g_blksum[i / SCAN_BLK];
    if (i == 0) g_rowptr[N_NODES] = N_EDGES;
}

__global__ void k_fill(const void* __restrict__ ei) {
    int e = blockIdx.x * blockDim.x + threadIdx.x;
    if (e >= N_EDGES) return;
    int d = edge_at(ei, e, 1);
    int pos = g_rowptr[d] + atomicAdd(&g_fill[d], 1);
    if (pos >= 0 && pos < N_EDGES) g_col[pos] = edge_at(ei, e, 0);
}

// ---------------------------------------------------------------------------
// SGEMM 128x128x8 fp32, f32x2 packed FMA, single-buffered (best measured).
// A stored PRE-DUPLICATED in smem (As[k][2r]=As[k][2r+1]=a_r) so the inner
// loop consumes {a,a} pairs directly — zero pack-movs in the hot loop:
// per k-step = 6 LDS + 32 FMA2 (was 4 LDS + 8 movs + 32 FMA2).
// Output is UNSCALED (dinv scaling moved into aggregation).
// ---------------------------------------------------------------------------
#define FMA_X2(acc, a2, b2) \
    asm("fma.rn.f32x2 %0, %1, %2, %0;" : "+l"(acc) : "l"(a2), "l"(b2))
#define UNPACK2(lo, hi, in) \
    asm("mov.b64 {%0, %1}, %2;" : "=r"(lo), "=r"(hi) : "l"(in))

template <int LAYER>
__global__ __launch_bounds__(256) void k_gemm(const float* __restrict__ Xin,
                                              const float* __restrict__ W)
{
    constexpr int N = (LAYER == 1) ? HID_C : OUT_C;
    constexpr int K = (LAYER == 1) ? IN_C  : HID_C;
    const float* __restrict__ A = (LAYER == 1) ? Xin : (const float*)g_X1;
    float* Hs = (LAYER == 1) ? g_Hs1 : g_Hs2;

    __shared__ float As[8][256];   // duplicated pairs: As[k][2r]=As[k][2r+1]
    __shared__ float Bs[8][128];

    const int tid = threadIdx.x;
    const int bm = blockIdx.x, bn = blockIdx.y;

    const int aRow = tid >> 1;          // 0..127
    const int aCol = (tid & 1) * 4;     // 0 or 4
    const int bRow = tid >> 5;          // 0..7
    const int bCol = (tid & 31) * 4;    // 0..124

    const int ty = tid >> 4;            // 0..15 -> 8 output rows each
    const int tx = tid & 15;            // 0..15 -> 8 output cols each

    const int gRowA = bm * 128 + aRow;
    const float* Aptr = A + (size_t)gRowA * K + aCol;
    const float* Bptr = W + (size_t)bRow * N + bn * 128 + bCol;

    unsigned long long acc[8][4];
    #pragma unroll
    for (int i = 0; i < 8; i++)
        #pragma unroll
        for (int j = 0; j < 4; j++) acc[i][j] = 0ull;

    for (int k0 = 0; k0 < K; k0 += 8) {
        float4 a4 = make_float4(0.f, 0.f, 0.f, 0.f);
        if (gRowA < N_NODES) a4 = *(const float4*)(Aptr + k0);
        *(float2*)&As[aCol + 0][2 * aRow] = make_float2(a4.x, a4.x);
        *(float2*)&As[aCol + 1][2 * aRow] = make_float2(a4.y, a4.y);
        *(float2*)&As[aCol + 2][2 * aRow] = make_float2(a4.z, a4.z);
        *(float2*)&As[aCol + 3][2 * aRow] = make_float2(a4.w, a4.w);

        float4 b4 = *(const float4*)(Bptr + (size_t)k0 * N);
        *(float4*)&Bs[bRow][bCol] = b4;

        __syncthreads();

        #pragma unroll
        for (int k = 0; k < 8; k++) {
            // A pairs: rows ty*8 .. ty*8+7, duplicated -> floats [ty*16, ty*16+16)
            ulonglong2 qa01 = *(const ulonglong2*)&As[k][ty * 16];
            ulonglong2 qa23 = *(const ulonglong2*)&As[k][ty * 16 + 4];
            ulonglong2 qa45 = *(const ulonglong2*)&As[k][ty * 16 + 8];
            ulonglong2 qa67 = *(const ulonglong2*)&As[k][ty * 16 + 12];
            ulonglong2 p0 = *(const ulonglong2*)&Bs[k][tx * 8];
            ulonglong2 p1 = *(const ulonglong2*)&Bs[k][tx * 8 + 4];
            #define ROWFMA(i, q) \
                FMA_X2(acc[i][0], q, p0.x); FMA_X2(acc[i][1], q, p0.y); \
                FMA_X2(acc[i][2], q, p1.x); FMA_X2(acc[i][3], q, p1.y)
            ROWFMA(0, qa01.x); ROWFMA(1, qa01.y);
            ROWFMA(2, qa23.x); ROWFMA(3, qa23.y);
            ROWFMA(4, qa45.x); ROWFMA(5, qa45.y);
            ROWFMA(6, qa67.x); ROWFMA(7, qa67.y);
            #undef ROWFMA
        }
        __syncthreads();
    }

    // Epilogue: unpack, store UNSCALED (dinv applied in aggregation)
    #pragma unroll
    for (int i = 0; i < 8; i++) {
        const int row = bm * 128 + ty * 8 + i;
        if (row >= N_NODES) continue;
        const size_t base = (size_t)row * N + bn * 128 + tx * 8;
        uint32_t u0, u1, u2, u3;
        UNPACK2(u0, u1, acc[i][0]);
        UNPACK2(u2, u3, acc[i][1]);
        float4 v0 = make_float4(__uint_as_float(u0), __uint_as_float(u1),
                                __uint_as_float(u2), __uint_as_float(u3));
        UNPACK2(u0, u1, acc[i][2]);
        UNPACK2(u2, u3, acc[i][3]);
        float4 v1 = make_float4(__uint_as_float(u0), __uint_as_float(u1),
                                __uint_as_float(u2), __uint_as_float(u3));
        *(float4*)(Hs + base)     = v0;
        *(float4*)(Hs + base + 4) = v1;
    }
}

// ---------------------------------------------------------------------------
// Aggregation (pure gather), unroll 4. dinv scaling applied HERE:
// out[d] = dinv[d] * ( dinv[d]*H[d] + sum_s dinv[s]*H[s] ) + bias
// ---------------------------------------------------------------------------
__global__ __launch_bounds__(128) void k_agg1(const float* __restrict__ bias) {
    const int d = blockIdx.x;
    const int t = threadIdx.x;                         // 128 = HID_C/4
    const float4* base = (const float4*)g_Hs1;
    const float dd = g_dinv[d];
    float4 self = base[(size_t)d * 128 + t];
    float4 acc;
    acc.x = self.x * dd; acc.y = self.y * dd;
    acc.z = self.z * dd; acc.w = self.w * dd;
    const int beg = g_rowptr[d], end = g_rowptr[d + 1];
    int j = beg;
    for (; j + 3 < end; j += 4) {
        int s0 = g_col[j], s1 = g_col[j + 1], s2 = g_col[j + 2], s3 = g_col[j + 3];
        float w0 = g_dinv[s0], w1 = g_dinv[s1], w2 = g_dinv[s2], w3 = g_dinv[s3];
        float4 v0 = base[(size_t)s0 * 128 + t];
        float4 v1 = base[(size_t)s1 * 128 + t];
        float4 v2 = base[(size_t)s2 * 128 + t];
        float4 v3 = base[(size_t)s3 * 128 + t];
        acc.x += (v0.x * w0 + v1.x * w1) + (v2.x * w2 + v3.x * w3);
        acc.y += (v0.y * w0 + v1.y * w1) + (v2.y * w2 + v3.y * w3);
        acc.z += (v0.z * w0 + v1.z * w1) + (v2.z * w2 + v3.z * w3);
        acc.w += (v0.w * w0 + v1.w * w1) + (v2.w * w2 + v3.w * w3);
    }
    for (; j < end; j++) {
        int s0 = g_col[j];
        float w0 = g_dinv[s0];
        float4 v0 = base[(size_t)s0 * 128 + t];
        acc.x += v0.x * w0; acc.y += v0.y * w0;
        acc.z += v0.z * w0; acc.w += v0.w * w0;
    }
    float4 b = ((const float4*)bias)[t];
    float4 r;
    r.x = fmaxf(acc.x * dd + b.x, 0.f);
    r.y = fmaxf(acc.y * dd + b.y, 0.f);
    r.z = fmaxf(acc.z * dd + b.z, 0.f);
    r.w = fmaxf(acc.w * dd + b.w, 0.f);
    ((float4*)g_X1)[(size_t)d * 128 + t] = r;
}

__global__ __launch_bounds__(64) void k_agg2(const float* __restrict__ bias,
                                             float* __restrict__ out) {
    const int d = blockIdx.x;
    const int t = threadIdx.x;                         // 64 = OUT_C/4
    const float4* base = (const float4*)g_Hs2;
    const float dd = g_dinv[d];
    float4 self = base[(size_t)d * 64 + t];
    float4 acc;
    acc.x = self.x * dd; acc.y = self.y * dd;
    acc.z = self.z * dd; acc.w = self.w * dd;
    const int beg = g_rowptr[d], end = g_rowptr[d + 1];
    int j = beg;
    for (; j + 3 < end; j += 4) {
        int s0 = g_col[j], s1 = g_col[j + 1], s2 = g_col[j + 2], s3 = g_col[j + 3];
        float w0 = g_dinv[s0], w1 = g_dinv[s1], w2 = g_dinv[s2], w3 = g_dinv[s3];
        float4 v0 = base[(size_t)s0 * 64 + t];
        float4 v1 = base[(size_t)s1 * 64 + t];
        float4 v2 = base[(size_t)s2 * 64 + t];
        float4 v3 = base[(size_t)s3 * 64 + t];
        acc.x += (v0.x * w0 + v1.x * w1) + (v2.x * w2 + v3.x * w3);
        acc.y += (v0.y * w0 + v1.y * w1) + (v2.y * w2 + v3.y * w3);
        acc.z += (v0.z * w0 + v1.z * w1) + (v2.z * w2 + v3.z * w3);
        acc.w += (v0.w * w0 + v1.w * w1) + (v2.w * w2 + v3.w * w3);
    }
    for (; j < end; j++) {
        int s0 = g_col[j];
        float w0 = g_dinv[s0];
        float4 v0 = base[(size_t)s0 * 64 + t];
        acc.x += v0.x * w0; acc.y += v0.y * w0;
        acc.z += v0.z * w0; acc.w += v0.w * w0;
    }
    float4 b = ((const float4*)bias)[t];
    float4 r;
    r.x = acc.x * dd + b.x;
    r.y = acc.y * dd + b.y;
    r.z = acc.z * dd + b.z;
    r.w = acc.w * dd + b.w;
    ((float4*)out)[(size_t)d * 64 + t] = r;
}

// ---------------------------------------------------------------------------
// Launch. gemm1 no longer depends on dinv, so it runs as MY 4th launch —
// the harness ncu capture consistently hits overall launch #6 (= 2 hidden
// + my #4), so next profile shows the GEMM instead of k_dinv.
// ---------------------------------------------------------------------------
extern "C" void kernel_launch(void* const* d_in, const int* in_sizes, int n_in,
                              void* d_out, int out_size)
{
    const float* x   = (const float*)d_in[0];
    const void*  ei  = d_in[1];                 // [2, E]; int32 or int64 (probed)
    const float* w1  = (const float*)d_in[2];
    const float* b1  = (const float*)d_in[3];
    const float* w2  = (const float*)d_in[4];
    const float* b2  = (const float*)d_in[5];
    float*       out = (float*)d_out;

    // 1-3) probe + CSR prep + degree count
    k_detect<<<1, 32>>>((const int*)ei);
    k_prep <<<(N_NODES + 255) / 256, 256>>>();
    k_count<<<(N_EDGES + 255) / 256, 256>>>(ei);

    // 4) Layer-1 GEMM (profiled launch)
    {
        dim3 grid((N_NODES + 127) / 128, HID_C / 128);
        k_gemm<1><<<grid, 256>>>(x, w1);
    }

    // 5-9) dinv + finish CSR build
    k_dinv <<<(N_NODES + 255) / 256, 256>>>();
    k_scan1<<<NB_SCAN, SCAN_BLK>>>();
    k_scan2<<<1, 128>>>();
    k_scan3<<<(N_NODES + 255) / 256, 256>>>();
    k_fill <<<(N_EDGES + 255) / 256, 256>>>(ei);

    // 10) layer-1 aggregation (applies dinv, bias, relu)
    k_agg1<<<N_NODES, 128>>>(b1);

    // 11) Layer-2 GEMM
    {
        dim3 grid((N_NODES + 127) / 128, OUT_C / 128);
        k_gemm<2><<<grid, 256>>>(x /*unused*/, w2);
    }
    // 12) layer-2 aggregation
    k_agg2<<<N_NODES, 64>>>(b2, out);
}